// round 11
// baseline (speedup 1.0000x reference)
#include <cuda_runtime.h>
#include <cstdint>

#define IN_FEATURES 8192
#define OUT_FEATURES 8192
#define THREADS 256
#define NWARPS (THREADS / 32)
#define F4_PER_ROW (IN_FEATURES / 4)          // 2048
#define F4_PER_THREAD (F4_PER_ROW / THREADS)  // 8

// dynamic smem: [trace row 32KB][x 32KB][partials 64B]
#define SMEM_BYTES (2 * F4_PER_ROW * 16 + 2 * NWARPS * 4)

__device__ __forceinline__ void cp_async16(void* smem_dst, const void* gmem_src) {
    uint32_t s = (uint32_t)__cvta_generic_to_shared(smem_dst);
    asm volatile("cp.async.cg.shared.global [%0], [%1], 16;\n" :: "r"(s), "l"(gmem_src) : "memory");
}

__global__ __launch_bounds__(THREADS)
void snn_fused_kernel(const float* __restrict__ x,
                      const float* __restrict__ states,
                      const float* __restrict__ mp,
                      const float* __restrict__ thr,
                      const float* __restrict__ trace,
                      float* __restrict__ out) {
    extern __shared__ float4 smem_dyn[];
    float4* str = smem_dyn;                         // trace row (cp.async)
    float4* sx  = smem_dyn + F4_PER_ROW;            // x (cp.async)
    float* warp_dot  = reinterpret_cast<float*>(smem_dyn + 2 * F4_PER_ROW);
    float* warp_wsum = warp_dot + NWARPS;

    const int o   = blockIdx.x;
    const int tid = threadIdx.x;

    const float4* x4  = reinterpret_cast<const float4*>(x);
    const float4* tr4 = reinterpret_cast<const float4*>(trace + (size_t)o * IN_FEATURES);
    const float4* st4 = reinterpret_cast<const float4*>(states + (size_t)o * IN_FEATURES);

    // Each thread stages exactly the elements it alone will read
    // (same tid + j*256 indexing everywhere) -> NO barriers needed for
    // either stage; per-thread cp.async group ordering suffices.

    // Group A: x (needed first; L2-hit for nearly all CTAs).
    #pragma unroll
    for (int j = 0; j < F4_PER_THREAD; j++) {
        const int i = tid + j * THREADS;
        cp_async16(&sx[i], &x4[i]);
    }
    asm volatile("cp.async.commit_group;\n" ::: "memory");

    // Group B: trace row (consumed after the reduction; overlaps everything).
    #pragma unroll
    for (int j = 0; j < F4_PER_THREAD; j++) {
        const int i = tid + j * THREADS;
        cp_async16(&str[i], &tr4[i]);
    }
    asm volatile("cp.async.commit_group;\n" ::: "memory");

    // Drain group A only (x landed; trace stays in flight).
    asm volatile("cp.async.wait_group 1;\n" ::: "memory");

    // ---- Phase 1: binary-weight dot product + connection count ----
    float dot = 0.0f, wsum = 0.0f;
    #pragma unroll
    for (int j = 0; j < F4_PER_THREAD; j++) {
        const int i = tid + j * THREADS;
        float4 s  = st4[i];
        float4 xv = sx[i];
        float w0 = (s.x > 50.0f) ? 1.0f : 0.0f;
        float w1 = (s.y > 50.0f) ? 1.0f : 0.0f;
        float w2 = (s.z > 50.0f) ? 1.0f : 0.0f;
        float w3 = (s.w > 50.0f) ? 1.0f : 0.0f;
        dot  += w0 * xv.x + w1 * xv.y + w2 * xv.z + w3 * xv.w;
        wsum += w0 + w1 + w2 + w3;
    }

    // Warp reduce
    #pragma unroll
    for (int off = 16; off > 0; off >>= 1) {
        dot  += __shfl_xor_sync(0xFFFFFFFFu, dot,  off);
        wsum += __shfl_xor_sync(0xFFFFFFFFu, wsum, off);
    }
    const int lane = tid & 31;
    const int wid  = tid >> 5;
    if (lane == 0) { warp_dot[wid] = dot; warp_wsum[wid] = wsum; }
    __syncthreads();   // the ONLY barrier in the kernel

    // All-thread redundant final reduce + epilogue.
    float d = 0.0f, ws = 0.0f;
    #pragma unroll
    for (int w = 0; w < NWARPS; w++) { d += warp_dot[w]; ws += warp_wsum[w]; }
    const float conn    = fmaxf(ws, 5.0f);
    const float current = d * (15.0f * rsqrtf(conn));
    const float v_mem   = mp[o] * 0.85f + current;
    const float t0      = thr[o];
    const float spike   = (v_mem >= t0) ? 1.0f : 0.0f;
    if (tid == 0) {
        const float new_v = v_mem * (1.0f - spike) * 0.1f;
        const float new_t = fminf(fmaxf(t0 + (spike - 0.1f) * 0.1f, 2.0f), 15.0f);
        out[o]                    = spike;   // spikes
        out[OUT_FEATURES + o]     = new_v;   // new membrane potential
        out[2 * OUT_FEATURES + o] = new_t;   // new adaptive threshold
    }

    // Drain group B (trace) — long since landed.
    asm volatile("cp.async.wait_group 0;\n" ::: "memory");

    // ---- Phase 2: all-smem reads, stores only to DRAM ----
    float4* ot4 = reinterpret_cast<float4*>(out + 3 * (size_t)OUT_FEATURES + (size_t)o * IN_FEATURES);
    #pragma unroll
    for (int j = 0; j < F4_PER_THREAD; j++) {
        const int i = tid + j * THREADS;
        float4 t  = str[i];
        float4 xv = sx[i];
        float4 r;
        r.x = fminf(fmaxf(t.x * 0.9f + spike * xv.x, 0.0f), 5.0f);
        r.y = fminf(fmaxf(t.y * 0.9f + spike * xv.y, 0.0f), 5.0f);
        r.z = fminf(fmaxf(t.z * 0.9f + spike * xv.z, 0.0f), 5.0f);
        r.w = fminf(fmaxf(t.w * 0.9f + spike * xv.w, 0.0f), 5.0f);
        __stcs(&ot4[i], r);
    }
}

extern "C" void kernel_launch(void* const* d_in, const int* in_sizes, int n_in,
                              void* d_out, int out_size) {
    const float* x      = (const float*)d_in[0];   // spike_input [8192]
    const float* states = (const float*)d_in[1];   // synapse_states [8192,8192]
    const float* mp     = (const float*)d_in[2];   // membrane_potential [8192]
    const float* thr    = (const float*)d_in[3];   // adaptive_threshold [8192]
    const float* trace  = (const float*)d_in[4];   // eligibility_trace [8192,8192]
    float* out          = (float*)d_out;

    cudaFuncSetAttribute(snn_fused_kernel,
                         cudaFuncAttributeMaxDynamicSharedMemorySize, SMEM_BYTES);
    snn_fused_kernel<<<OUT_FEATURES, THREADS, SMEM_BYTES>>>(x, states, mp, thr, trace, out);
}

// round 12
// speedup vs baseline: 1.0142x; 1.0142x over previous
#include <cuda_runtime.h>

#define IN_FEATURES 8192
#define OUT_FEATURES 8192
#define THREADS 256
#define NWARPS (THREADS / 32)
#define F4_PER_ROW (IN_FEATURES / 4)          // 2048
#define F4_PER_THREAD (F4_PER_ROW / THREADS)  // 8

__global__ __launch_bounds__(THREADS, 2)
void snn_fused_kernel(const float* __restrict__ x,
                      const float* __restrict__ states,
                      const float* __restrict__ mp,
                      const float* __restrict__ thr,
                      const float* __restrict__ trace,
                      float* __restrict__ out) {
    __shared__ float4 sx[F4_PER_ROW];   // 32 KB staged spike input
    __shared__ float warp_dot[NWARPS];
    __shared__ float warp_wsum[NWARPS];

    const int o   = blockIdx.x;
    const int tid = threadIdx.x;

    // Hoist the two scalar epilogue inputs to the very top: they are
    // independent of all other work, and ptxas will NOT hoist them across
    // the BAR.SYNC if left in the epilogue. This removes an L2-latency
    // stall from the post-barrier critical path.
    const float mp_o  = __ldg(&mp[o]);
    const float thr_o = __ldg(&thr[o]);

    // Stage x into shared memory (L2-resident broadcast).
    const float4* x4 = reinterpret_cast<const float4*>(x);
    #pragma unroll
    for (int j = 0; j < F4_PER_THREAD; j++) {
        sx[tid + j * THREADS] = x4[tid + j * THREADS];
    }
    __syncthreads();

    // ---- Phase 1: binary-weight dot product + connection count ----
    const float4* st4 = reinterpret_cast<const float4*>(states + (size_t)o * IN_FEATURES);
    float dot = 0.0f, wsum = 0.0f;
    #pragma unroll
    for (int j = 0; j < F4_PER_THREAD; j++) {
        const int i = tid + j * THREADS;
        float4 s  = st4[i];
        float4 xv = sx[i];
        float w0 = (s.x > 50.0f) ? 1.0f : 0.0f;
        float w1 = (s.y > 50.0f) ? 1.0f : 0.0f;
        float w2 = (s.z > 50.0f) ? 1.0f : 0.0f;
        float w3 = (s.w > 50.0f) ? 1.0f : 0.0f;
        dot  += w0 * xv.x + w1 * xv.y + w2 * xv.z + w3 * xv.w;
        wsum += w0 + w1 + w2 + w3;
    }

    // Warp reduce
    #pragma unroll
    for (int off = 16; off > 0; off >>= 1) {
        dot  += __shfl_xor_sync(0xFFFFFFFFu, dot,  off);
        wsum += __shfl_xor_sync(0xFFFFFFFFu, wsum, off);
    }
    const int lane = tid & 31;
    const int wid  = tid >> 5;
    if (lane == 0) { warp_dot[wid] = dot; warp_wsum[wid] = wsum; }
    __syncthreads();   // the single barrier: partials published

    // All-thread redundant final reduce + epilogue (pure smem + ALU now).
    float d = 0.0f, ws = 0.0f;
    #pragma unroll
    for (int w = 0; w < NWARPS; w++) { d += warp_dot[w]; ws += warp_wsum[w]; }
    const float conn    = fmaxf(ws, 5.0f);
    const float current = d * (15.0f * rsqrtf(conn));
    const float v_mem   = mp_o * 0.85f + current;
    const float spike   = (v_mem >= thr_o) ? 1.0f : 0.0f;
    if (tid == 0) {
        const float new_v = v_mem * (1.0f - spike) * 0.1f;
        const float new_t = fminf(fmaxf(thr_o + (spike - 0.1f) * 0.1f, 2.0f), 15.0f);
        out[o]                    = spike;   // spikes
        out[OUT_FEATURES + o]     = new_v;   // new membrane potential
        out[2 * OUT_FEATURES + o] = new_t;   // new adaptive threshold
    }

    // ---- Phase 2: eligibility-trace update ----
    const float4* tr4 = reinterpret_cast<const float4*>(trace + (size_t)o * IN_FEATURES);
    float4* ot4 = reinterpret_cast<float4*>(out + 3 * (size_t)OUT_FEATURES + (size_t)o * IN_FEATURES);
    #pragma unroll
    for (int j = 0; j < F4_PER_THREAD; j++) {
        const int i = tid + j * THREADS;
        float4 t  = tr4[i];
        float4 xv = sx[i];
        float4 r;
        r.x = fminf(fmaxf(t.x * 0.9f + spike * xv.x, 0.0f), 5.0f);
        r.y = fminf(fmaxf(t.y * 0.9f + spike * xv.y, 0.0f), 5.0f);
        r.z = fminf(fmaxf(t.z * 0.9f + spike * xv.z, 0.0f), 5.0f);
        r.w = fminf(fmaxf(t.w * 0.9f + spike * xv.w, 0.0f), 5.0f);
        __stcs(&ot4[i], r);
    }
}

extern "C" void kernel_launch(void* const* d_in, const int* in_sizes, int n_in,
                              void* d_out, int out_size) {
    const float* x      = (const float*)d_in[0];   // spike_input [8192]
    const float* states = (const float*)d_in[1];   // synapse_states [8192,8192]
    const float* mp     = (const float*)d_in[2];   // membrane_potential [8192]
    const float* thr    = (const float*)d_in[3];   // adaptive_threshold [8192]
    const float* trace  = (const float*)d_in[4];   // eligibility_trace [8192,8192]
    float* out          = (float*)d_out;

    snn_fused_kernel<<<OUT_FEATURES, THREADS>>>(x, states, mp, thr, trace, out);
}